// round 10
// baseline (speedup 1.0000x reference)
#include <cuda_runtime.h>
#include <cuda_fp16.h>
#include <cstdint>

// ---------------------------------------------------------------------------
// Problem constants
// ---------------------------------------------------------------------------
#define IN_F   4096
#define OUT_F  4096
#define NBLKS  128      // IN_F / 32
#define MROWS  16384    // 4 * 4096 tokens

// Scratch (allocation-free rule: __device__ globals)
__device__ float  g_Q[NBLKS * 32 * 32];             // 512 KB
__device__ __half g_W2h[(size_t)OUT_F * IN_F];      // 32 MB  rotated+dequantized W, fp16
__device__ __half g_Xh[(size_t)MROWS * IN_F];       // 128 MB x in fp16

// ---------------------------------------------------------------------------
// Helpers
// ---------------------------------------------------------------------------
__device__ __forceinline__ uint32_t smem_u32(const void* p) {
    uint32_t a;
    asm("{ .reg .u64 t; cvta.to.shared.u64 t, %1; cvt.u32.u64 %0, t; }" : "=r"(a) : "l"(p));
    return a;
}

__device__ __forceinline__ void cp16(uint32_t s, const void* g) {
    asm volatile("cp.async.cg.shared.global [%0], [%1], 16;" :: "r"(s), "l"(g));
}
#define CP_COMMIT() asm volatile("cp.async.commit_group;" ::: "memory")
#define CP_WAIT(n)  asm volatile("cp.async.wait_group %0;" :: "n"(n) : "memory")

#define LDM_X4(R, addr) \
    asm volatile("ldmatrix.sync.aligned.m8n8.x4.shared.b16 {%0,%1,%2,%3}, [%4];" \
                 : "=r"((R)[0]), "=r"((R)[1]), "=r"((R)[2]), "=r"((R)[3]) : "r"(addr))

__device__ __forceinline__ void mma_f16(float c[4], const uint32_t a[4], uint32_t b0, uint32_t b1) {
    asm volatile(
        "mma.sync.aligned.m16n8k16.row.col.f32.f16.f16.f32 "
        "{%0,%1,%2,%3}, {%4,%5,%6,%7}, {%8,%9}, {%0,%1,%2,%3};"
        : "+f"(c[0]), "+f"(c[1]), "+f"(c[2]), "+f"(c[3])
        : "r"(a[0]), "r"(a[1]), "r"(a[2]), "r"(a[3]), "r"(b0), "r"(b1));
}

// ---------------------------------------------------------------------------
// Kernel 1: Cayley  Q = (I-S)^{-1}(I+S)   (Gauss-Jordan, diag-dominant, no pivot)
// ---------------------------------------------------------------------------
__global__ void cayley_kernel(const float* __restrict__ oft_r) {
    __shared__ float A[32][33];
    __shared__ float Bm[32][33];
    int n = blockIdx.x;
    int j = threadIdx.x, i = threadIdx.y;
    const float* R = oft_r + n * 1024;
    float s  = 0.5f * (R[i * 32 + j] - R[j * 32 + i]);
    float id = (i == j) ? 1.0f : 0.0f;
    A[i][j]  = id - s;
    Bm[i][j] = id + s;
    __syncthreads();
    for (int k = 0; k < 32; k++) {
        float fac = A[i][k] / A[k][k];
        __syncthreads();
        if (i != k) {
            A[i][j]  = fmaf(-fac, A[k][j],  A[i][j]);
            Bm[i][j] = fmaf(-fac, Bm[k][j], Bm[i][j]);
        }
        __syncthreads();
    }
    g_Q[n * 1024 + i * 32 + j] = Bm[i][j] / A[i][i];
}

// ---------------------------------------------------------------------------
// Kernel 2 (fused prep): blocks [0, XBLKS) convert x -> fp16;
// blocks [XBLKS, XBLKS+65536) dequant + fold rotation into W (fp16 out).
// ---------------------------------------------------------------------------
#define XBLKS 65536     // MROWS*IN_F / (256*4)

__global__ __launch_bounds__(256) void prep_kernel(
    const float* __restrict__ x, const int* __restrict__ codes,
    const float* __restrict__ codebooks, const float* __restrict__ scales)
{
    __shared__ float Qs[32][33];
    int blk = blockIdx.x;
    if (blk < XBLKS) {
        size_t i = ((size_t)blk * 256 + threadIdx.x) * 4;
        float4 v = *(const float4*)(x + i);
        *(__half2*)(g_Xh + i)     = __floats2half2_rn(v.x, v.y);
        *(__half2*)(g_Xh + i + 2) = __floats2half2_rn(v.z, v.w);
        return;
    }
    blk -= XBLKS;
    int n = blk & 127;                 // 0..127
    int obase = (blk >> 7) * 8;
    int tid = threadIdx.x;
    int w = tid >> 5, lane = tid & 31;

    for (int idx = tid; idx < 1024; idx += 256)
        Qs[idx >> 5][idx & 31] = g_Q[n * 1024 + idx];
    __syncthreads();

    int o = obase + w;
    int grp = 4 * n + (lane >> 3);
    int code = codes[o * 512 + grp];
    float wv = codebooks[code * 8 + (lane & 7)];

    float acc = 0.f;
    #pragma unroll
    for (int kk = 0; kk < 32; kk++) {
        float wk = __shfl_sync(0xFFFFFFFFu, wv, kk);
        acc = fmaf(Qs[lane][kk], wk, acc);
    }
    acc *= scales[o];
    g_W2h[(size_t)o * IN_F + n * 32 + lane] = __float2half_rn(acc);
}

// ---------------------------------------------------------------------------
// Kernel 3: PERSISTENT fp16 mma.sync GEMM  out = x @ W2^T + bias (fp32 acc)
// Grid = 148 CTAs (1/SM); each walks tiles bid, bid+148, ... The cp.async
// pipeline runs continuously ACROSS tile boundaries (fill cursor 2 k-iters
// ahead of compute): prologue paid once per CTA, epilogue overlaps next
// tile's loads.
// CTA tile 128x256, 256 threads, warp 64x64. KBLK=128 as two 64-wide halves
// (keeps proven 128B-row j^(row&7) swizzle). STAGES=2 x 96KB = 192KB SMEM.
// One CP_WAIT(0)+barrier per 4096 tensor-cycles.
// RF: ~230 regs x 256 thr = 59K < 64K (R8 lesson, checked).
// ---------------------------------------------------------------------------
#define KBLK   128
#define TM     128
#define TN     256
#define KIT_T  (IN_F / KBLK)            // 32 k-iters per tile
#define NT_N   (OUT_F / TN)             // 16
#define NTILES ((MROWS / TM) * NT_N)    // 2048
#define GRID   148
#define A_HALF 16384                    // 128 rows x 128B per K-half
#define B_HALF 32768                    // 256 rows x 128B per K-half
#define A_BYTES (2 * A_HALF)            // 32 KB
#define STAGE_BYTES (A_BYTES + 2 * B_HALF)  // 96 KB

__device__ __forceinline__ uint32_t swz(int row, int j) {
    return (uint32_t)(row * 128 + ((j ^ (row & 7)) << 4));
}

// Fill one 96KB stage: A[128][128B]x2 halves + B[256][128B]x2 halves.
// Per thread: r0 = tid>>3 (0..31), j0 = tid&7; 8 A-chunks + 16 B-chunks.
__device__ __forceinline__ void stage_fill(uint32_t sb,
        const __half* gA, const __half* gB, uint32_t so0, int kb)
{
    #pragma unroll
    for (int h = 0; h < 2; h++)
        #pragma unroll
        for (int p = 0; p < 4; p++)
            cp16(sb + h * A_HALF + so0 + p * 4096,
                 gA + (size_t)p * 32 * IN_F + kb + h * 64);
    #pragma unroll
    for (int h = 0; h < 2; h++)
        #pragma unroll
        for (int p = 0; p < 8; p++)
            cp16(sb + A_BYTES + h * B_HALF + so0 + p * 4096,
                 gB + (size_t)p * 32 * IN_F + kb + h * 64);
}

__device__ __forceinline__ void frag_load(uint32_t a[4][4], uint32_t b[4][4],
                                          uint32_t Ab, uint32_t Bb,
                                          uint32_t aoff, uint32_t boff)
{
    #pragma unroll
    for (int mi = 0; mi < 4; mi++) LDM_X4(a[mi], Ab + aoff + mi * 2048);
    #pragma unroll
    for (int p = 0; p < 4; p++)    LDM_X4(b[p], Bb + boff + p * 2048);
}

__device__ __forceinline__ void mma_block(float acc[4][8][4],
                                          const uint32_t a[4][4], const uint32_t b[4][4])
{
    #pragma unroll
    for (int mi = 0; mi < 4; mi++)
        #pragma unroll
        for (int p = 0; p < 4; p++) {
            mma_f16(acc[mi][2 * p],     a[mi], b[p][0], b[p][2]);
            mma_f16(acc[mi][2 * p + 1], a[mi], b[p][1], b[p][3]);
        }
}

__global__ __launch_bounds__(256, 1)
void gemm_kernel(const float* __restrict__ bias, float* __restrict__ out)
{
    extern __shared__ char smem[];
    uint32_t sbase = smem_u32(smem);
    uint32_t bufs0 = sbase, bufs1 = sbase + STAGE_BYTES;

    int tid  = threadIdx.x;
    int wid  = tid >> 5, lane = tid & 31;
    int g    = lane >> 2, tig = lane & 3;
    int lr   = lane & 7;
    int q    = lane >> 3;
    int wm   = (wid >> 2) * 64;
    int wn   = (wid & 3) * 64;

    // ldmatrix offsets within a K-half: substep u (0..3) uses chunks 2u,2u+1.
    int ra = wm + lr + ((q & 1) << 3);
    int rb = wn + lr + ((q & 1) << 3);
    int ja = q >> 1;
    uint32_t aoff[4], boff[4];
    #pragma unroll
    for (int u = 0; u < 4; u++) {
        aoff[u] = swz(ra, 2 * u + ja);
        boff[u] = swz(rb, 2 * u + ja);
    }

    // Global fill mapping.
    int r0 = tid >> 3, j0 = tid & 7;
    uint32_t so0 = swz(r0, j0);

    // Fill-side cursor (2 k-iters ahead of compute).
    int tile   = blockIdx.x;
    int f_tile = tile, f_k = 0;
    const __half* fgA = g_Xh  + (size_t)((f_tile >> 4) * TM + r0) * IN_F + j0 * 8;
    const __half* fgB = g_W2h + (size_t)((f_tile & 15) * TN + r0) * IN_F + j0 * 8;

    float acc[4][8][4];
    #pragma unroll
    for (int mi = 0; mi < 4; mi++)
        #pragma unroll
        for (int ni = 0; ni < 8; ni++)
            #pragma unroll
            for (int p = 0; p < 4; p++) acc[mi][ni][p] = 0.f;

    if (tile >= NTILES) return;

    // Prologue: fill both stages (k-iters 0,1 of first tile).
    stage_fill(bufs0, fgA, fgB, so0, 0);
    CP_COMMIT();
    stage_fill(bufs1, fgA, fgB, so0, KBLK);
    CP_COMMIT();
    f_k = 2;
    CP_WAIT(1);
    __syncthreads();

    uint32_t fa[2][4][4], fb[2][4][4];
    frag_load(fa[0], fb[0], bufs0, bufs0 + A_BYTES, aoff[0], boff[0]);

    int buf = 0;
    for (; tile < NTILES; tile += GRID) {
        for (int kk = 0; kk < KIT_T; kk++) {
            uint32_t cb = buf ? bufs1 : bufs0;
            uint32_t ob = buf ? bufs0 : bufs1;
            #pragma unroll
            for (int s = 0; s < 8; s++) {
                if (s < 7) {
                    int t = s + 1, h = t >> 2, u = t & 3;
                    frag_load(fa[t & 1], fb[t & 1],
                              cb + h * A_HALF, cb + A_BYTES + h * B_HALF,
                              aoff[u], boff[u]);
                } else {
                    CP_WAIT(0);                 // own prev group (ob data) done
                    __syncthreads();            // all threads' data visible; all done reading cb
                    if (f_tile < NTILES) {
                        stage_fill(cb, fgA, fgB, so0, f_k * KBLK);
                        if (++f_k == KIT_T) {
                            f_k = 0;
                            f_tile += GRID;
                            if (f_tile < NTILES) {
                                fgA = g_Xh  + (size_t)((f_tile >> 4) * TM + r0) * IN_F + j0 * 8;
                                fgB = g_W2h + (size_t)((f_tile & 15) * TN + r0) * IN_F + j0 * 8;
                            }
                        }
                    }
                    CP_COMMIT();
                    frag_load(fa[0], fb[0], ob, ob + A_BYTES, aoff[0], boff[0]);
                }
                mma_block(acc, fa[s & 1], fb[s & 1]);
            }
            buf ^= 1;
        }

        // Epilogue for this tile (overlaps next tile's in-flight fills).
        int mbase = (tile >> 4) * TM, nbase = (tile & 15) * TN;
        #pragma unroll
        for (int mi = 0; mi < 4; mi++) {
            int r = mbase + wm + mi * 16 + g;
            #pragma unroll
            for (int ni = 0; ni < 8; ni++) {
                int col = nbase + wn + ni * 8 + tig * 2;
                float2 bv = *(const float2*)(bias + col);
                float2 v0 = make_float2(acc[mi][ni][0] + bv.x, acc[mi][ni][1] + bv.y);
                float2 v1 = make_float2(acc[mi][ni][2] + bv.x, acc[mi][ni][3] + bv.y);
                *(float2*)(out + (size_t)r * OUT_F + col)       = v0;
                *(float2*)(out + (size_t)(r + 8) * OUT_F + col) = v1;
                acc[mi][ni][0] = acc[mi][ni][1] = acc[mi][ni][2] = acc[mi][ni][3] = 0.f;
            }
        }
    }
}

// ---------------------------------------------------------------------------
// Launch
// ---------------------------------------------------------------------------
extern "C" void kernel_launch(void* const* d_in, const int* in_sizes, int n_in,
                              void* d_out, int out_size)
{
    const float* x         = (const float*)d_in[0];
    const float* oft_r     = (const float*)d_in[1];
    const int*   codes     = (const int*)d_in[2];
    const float* codebooks = (const float*)d_in[3];
    const float* scales    = (const float*)d_in[4];
    const float* bias      = (const float*)d_in[5];
    float*       out       = (float*)d_out;

    cayley_kernel<<<NBLKS, dim3(32, 32)>>>(oft_r);
    prep_kernel<<<XBLKS + NBLKS * (OUT_F / 8), 256>>>(x, codes, codebooks, scales);

    int smem_bytes = 2 * STAGE_BYTES;   // 192 KB
    cudaFuncSetAttribute(gemm_kernel, cudaFuncAttributeMaxDynamicSharedMemorySize, smem_bytes);
    gemm_kernel<<<GRID, 256, smem_bytes>>>(bias, out);
}

// round 11
// speedup vs baseline: 1.0090x; 1.0090x over previous
#include <cuda_runtime.h>
#include <cuda_fp16.h>
#include <cstdint>

// ---------------------------------------------------------------------------
// Problem constants
// ---------------------------------------------------------------------------
#define IN_F   4096
#define OUT_F  4096
#define NBLKS  128      // IN_F / 32
#define MROWS  16384    // 4 * 4096 tokens

// Scratch (allocation-free rule: __device__ globals)
__device__ float  g_Q[NBLKS * 32 * 32];             // 512 KB
__device__ __half g_W2h[(size_t)OUT_F * IN_F];      // 32 MB  rotated+dequantized W, fp16
__device__ __half g_Xh[(size_t)MROWS * IN_F];       // 128 MB x in fp16

// ---------------------------------------------------------------------------
// Helpers
// ---------------------------------------------------------------------------
__device__ __forceinline__ uint32_t smem_u32(const void* p) {
    uint32_t a;
    asm("{ .reg .u64 t; cvta.to.shared.u64 t, %1; cvt.u32.u64 %0, t; }" : "=r"(a) : "l"(p));
    return a;
}

__device__ __forceinline__ void cp16(uint32_t s, const void* g) {
    asm volatile("cp.async.cg.shared.global [%0], [%1], 16;" :: "r"(s), "l"(g));
}
#define CP_COMMIT() asm volatile("cp.async.commit_group;" ::: "memory")
#define CP_WAIT(n)  asm volatile("cp.async.wait_group %0;" :: "n"(n) : "memory")

#define LDM_X4(R, addr) \
    asm volatile("ldmatrix.sync.aligned.m8n8.x4.shared.b16 {%0,%1,%2,%3}, [%4];" \
                 : "=r"((R)[0]), "=r"((R)[1]), "=r"((R)[2]), "=r"((R)[3]) : "r"(addr))

__device__ __forceinline__ void mma_f16(float c[4], const uint32_t a[4], uint32_t b0, uint32_t b1) {
    asm volatile(
        "mma.sync.aligned.m16n8k16.row.col.f32.f16.f16.f32 "
        "{%0,%1,%2,%3}, {%4,%5,%6,%7}, {%8,%9}, {%0,%1,%2,%3};"
        : "+f"(c[0]), "+f"(c[1]), "+f"(c[2]), "+f"(c[3])
        : "r"(a[0]), "r"(a[1]), "r"(a[2]), "r"(a[3]), "r"(b0), "r"(b1));
}

// ---------------------------------------------------------------------------
// Kernel 1: Cayley  Q = (I-S)^{-1}(I+S)   (Gauss-Jordan, diag-dominant, no pivot)
// ---------------------------------------------------------------------------
__global__ void cayley_kernel(const float* __restrict__ oft_r) {
    __shared__ float A[32][33];
    __shared__ float Bm[32][33];
    int n = blockIdx.x;
    int j = threadIdx.x, i = threadIdx.y;
    const float* R = oft_r + n * 1024;
    float s  = 0.5f * (R[i * 32 + j] - R[j * 32 + i]);
    float id = (i == j) ? 1.0f : 0.0f;
    A[i][j]  = id - s;
    Bm[i][j] = id + s;
    __syncthreads();
    for (int k = 0; k < 32; k++) {
        float fac = A[i][k] / A[k][k];
        __syncthreads();
        if (i != k) {
            A[i][j]  = fmaf(-fac, A[k][j],  A[i][j]);
            Bm[i][j] = fmaf(-fac, Bm[k][j], Bm[i][j]);
        }
        __syncthreads();
    }
    g_Q[n * 1024 + i * 32 + j] = Bm[i][j] / A[i][i];
}

// ---------------------------------------------------------------------------
// Kernel 2 (fused prep): blocks [0, XBLKS) convert x -> fp16;
// blocks [XBLKS, XBLKS+65536) dequant + fold rotation into W (fp16 out).
// ---------------------------------------------------------------------------
#define XBLKS 65536     // MROWS*IN_F / (256*4)

__global__ __launch_bounds__(256) void prep_kernel(
    const float* __restrict__ x, const int* __restrict__ codes,
    const float* __restrict__ codebooks, const float* __restrict__ scales)
{
    __shared__ float Qs[32][33];
    int blk = blockIdx.x;
    if (blk < XBLKS) {
        size_t i = ((size_t)blk * 256 + threadIdx.x) * 4;
        float4 v = *(const float4*)(x + i);
        *(__half2*)(g_Xh + i)     = __floats2half2_rn(v.x, v.y);
        *(__half2*)(g_Xh + i + 2) = __floats2half2_rn(v.z, v.w);
        return;
    }
    blk -= XBLKS;
    int n = blk & 127;                 // 0..127
    int obase = (blk >> 7) * 8;
    int tid = threadIdx.x;
    int w = tid >> 5, lane = tid & 31;

    for (int idx = tid; idx < 1024; idx += 256)
        Qs[idx >> 5][idx & 31] = g_Q[n * 1024 + idx];
    __syncthreads();

    int o = obase + w;
    int grp = 4 * n + (lane >> 3);
    int code = codes[o * 512 + grp];
    float wv = codebooks[code * 8 + (lane & 7)];

    float acc = 0.f;
    #pragma unroll
    for (int kk = 0; kk < 32; kk++) {
        float wk = __shfl_sync(0xFFFFFFFFu, wv, kk);
        acc = fmaf(Qs[lane][kk], wk, acc);
    }
    acc *= scales[o];
    g_W2h[(size_t)o * IN_F + n * 32 + lane] = __float2half_rn(acc);
}

// ---------------------------------------------------------------------------
// Kernel 3: PERSISTENT fp16 mma.sync GEMM  out = x @ W2^T + bias (fp32 acc)
// EXACTLY the R9 pipeline (3 stages x 48KB, KBLK=64, CP_WAIT(1), same swizzle
// and fragment schedule) — only the fill cursor is generalized to roll across
// tile boundaries. Grid = 148 CTAs; tile walk bid, bid+148, ...
// Prologue paid once per CTA; epilogue overlaps next tile's in-flight fills.
// RF: ~225 regs x 256 thr = 58K < 64K. SMEM 144 KB.
// ---------------------------------------------------------------------------
#define STAGES 3
#define KBLK   64
#define TM     128
#define TN     256
#define KIT_T  (IN_F / KBLK)            // 64 k-iters per tile
#define NT_N   (OUT_F / TN)             // 16
#define NTILES ((MROWS / TM) * NT_N)    // 2048
#define GRID   148
#define A_BYTES (TM * KBLK * 2)         // 16 KB
#define B_BYTES (TN * KBLK * 2)         // 32 KB
#define STAGE_BYTES (A_BYTES + B_BYTES) // 48 KB

__device__ __forceinline__ uint32_t swz(int row, int j) {
    return (uint32_t)(row * 128 + ((j ^ (row & 7)) << 4));
}

__device__ __forceinline__ void stage_fill(uint32_t sb,
        const __half* gA, const __half* gB, uint32_t so0, int kb)
{
    #pragma unroll
    for (int p = 0; p < 4; p++)
        cp16(sb + so0 + p * 4096,           gA + (size_t)p * 32 * IN_F + kb);
    #pragma unroll
    for (int p = 0; p < 8; p++)
        cp16(sb + A_BYTES + so0 + p * 4096, gB + (size_t)p * 32 * IN_F + kb);
}

__device__ __forceinline__ void frag_load(uint32_t a[4][4], uint32_t b[4][4],
                                          uint32_t sb, uint32_t aoff, uint32_t boff)
{
    #pragma unroll
    for (int mi = 0; mi < 4; mi++) LDM_X4(a[mi], sb + aoff + mi * 2048);
    #pragma unroll
    for (int p = 0; p < 4; p++)    LDM_X4(b[p], sb + A_BYTES + boff + p * 2048);
}

__device__ __forceinline__ void mma_block(float acc[4][8][4],
                                          const uint32_t a[4][4], const uint32_t b[4][4])
{
    #pragma unroll
    for (int mi = 0; mi < 4; mi++)
        #pragma unroll
        for (int p = 0; p < 4; p++) {
            mma_f16(acc[mi][2 * p],     a[mi], b[p][0], b[p][2]);
            mma_f16(acc[mi][2 * p + 1], a[mi], b[p][1], b[p][3]);
        }
}

__global__ __launch_bounds__(256, 1)
void gemm_kernel(const float* __restrict__ bias, float* __restrict__ out)
{
    extern __shared__ char smem[];
    uint32_t sbase = smem_u32(smem);
    uint32_t buf_lim = sbase + 2 * STAGE_BYTES;      // last stage base

    int tid  = threadIdx.x;
    int wid  = tid >> 5, lane = tid & 31;
    int g    = lane >> 2, tig = lane & 3;
    int lr   = lane & 7;
    int q    = lane >> 3;
    int wm   = (wid >> 2) * 64;
    int wn   = (wid & 3) * 64;

    // ldmatrix offsets: substep s uses 16B chunks 2s, 2s+1.
    int ra = wm + lr + ((q & 1) << 3);
    int rb = wn + lr + ((q & 1) << 3);
    int ja = q >> 1;
    uint32_t aoff[4], boff[4];
    #pragma unroll
    for (int s = 0; s < 4; s++) {
        aoff[s] = swz(ra, 2 * s + ja);
        boff[s] = swz(rb, 2 * s + ja);
    }

    // Global fill mapping: thread -> (row r0 = tid>>3, chunk j0 = tid&7).
    int r0 = tid >> 3, j0 = tid & 7;
    uint32_t so0 = swz(r0, j0);

    int tile = blockIdx.x;
    if (tile >= NTILES) return;

    // Fill-side cursor, 2 k-iters ahead of compute.
    int f_tile = tile, f_k = 0;
    const __half* fgA = g_Xh  + (size_t)((f_tile >> 4) * TM + r0) * IN_F + j0 * 8;
    const __half* fgB = g_W2h + (size_t)((f_tile & 15) * TN + r0) * IN_F + j0 * 8;

    // Flat iteration count for this CTA (to guard the tail frag_load).
    int my_tiles = (NTILES - tile + GRID - 1) / GRID;
    int total_it = my_tiles * KIT_T;
    int it = 0;

    float acc[4][8][4];
    #pragma unroll
    for (int mi = 0; mi < 4; mi++)
        #pragma unroll
        for (int ni = 0; ni < 8; ni++)
            #pragma unroll
            for (int p = 0; p < 4; p++) acc[mi][ni][p] = 0.f;

    // Prologue: fill stages 0,1 (tile, k=0,1); cursor advances to k=2.
    stage_fill(sbase,               fgA, fgB, so0, 0);
    CP_COMMIT();
    stage_fill(sbase + STAGE_BYTES, fgA, fgB, so0, KBLK);
    CP_COMMIT();
    f_k = 2;
    CP_WAIT(1);
    __syncthreads();

    uint32_t fa[2][4][4], fb[2][4][4];
    frag_load(fa[0], fb[0], sbase, aoff[0], boff[0]);

    uint32_t sb_read = sbase;                // compute buffer (k)
    uint32_t sb_fill = buf_lim;              // fill buffer (k+2)

    for (; tile < NTILES; tile += GRID) {
        for (int kk = 0; kk < KIT_T; kk++, it++) {
            if (f_tile < NTILES) {
                stage_fill(sb_fill, fgA, fgB, so0, f_k * KBLK);
                if (++f_k == KIT_T) {
                    f_k = 0;
                    f_tile += GRID;
                    if (f_tile < NTILES) {
                        fgA = g_Xh  + (size_t)((f_tile >> 4) * TM + r0) * IN_F + j0 * 8;
                        fgB = g_W2h + (size_t)((f_tile & 15) * TN + r0) * IN_F + j0 * 8;
                    }
                }
            }
            CP_COMMIT();                     // one group per k-iter, always

            #pragma unroll
            for (int s = 0; s < 4; s++) {
                if (s < 3) {
                    frag_load(fa[(s + 1) & 1], fb[(s + 1) & 1], sb_read, aoff[s + 1], boff[s + 1]);
                } else {
                    CP_WAIT(1);              // next k-iter's buffer landed
                    __syncthreads();
                    if (it + 1 < total_it) {
                        uint32_t nxt = (sb_read == buf_lim) ? sbase : sb_read + STAGE_BYTES;
                        frag_load(fa[0], fb[0], nxt, aoff[0], boff[0]);
                    }
                }
                mma_block(acc, fa[s & 1], fb[s & 1]);
            }

            sb_read = (sb_read == buf_lim) ? sbase : sb_read + STAGE_BYTES;
            sb_fill = (sb_fill == buf_lim) ? sbase : sb_fill + STAGE_BYTES;
        }

        // Epilogue (overlaps next tile's in-flight fills).
        int mbase = (tile >> 4) * TM, nbase = (tile & 15) * TN;
        #pragma unroll
        for (int mi = 0; mi < 4; mi++) {
            int r = mbase + wm + mi * 16 + g;
            #pragma unroll
            for (int ni = 0; ni < 8; ni++) {
                int col = nbase + wn + ni * 8 + tig * 2;
                float2 bv = *(const float2*)(bias + col);
                float2 v0 = make_float2(acc[mi][ni][0] + bv.x, acc[mi][ni][1] + bv.y);
                float2 v1 = make_float2(acc[mi][ni][2] + bv.x, acc[mi][ni][3] + bv.y);
                *(float2*)(out + (size_t)r * OUT_F + col)       = v0;
                *(float2*)(out + (size_t)(r + 8) * OUT_F + col) = v1;
                acc[mi][ni][0] = acc[mi][ni][1] = acc[mi][ni][2] = acc[mi][ni][3] = 0.f;
            }
        }
    }
}

// ---------------------------------------------------------------------------
// Launch
// ---------------------------------------------------------------------------
extern "C" void kernel_launch(void* const* d_in, const int* in_sizes, int n_in,
                              void* d_out, int out_size)
{
    const float* x         = (const float*)d_in[0];
    const float* oft_r     = (const float*)d_in[1];
    const int*   codes     = (const int*)d_in[2];
    const float* codebooks = (const float*)d_in[3];
    const float* scales    = (const float*)d_in[4];
    const float* bias      = (const float*)d_in[5];
    float*       out       = (float*)d_out;

    cayley_kernel<<<NBLKS, dim3(32, 32)>>>(oft_r);
    prep_kernel<<<XBLKS + NBLKS * (OUT_F / 8), 256>>>(x, codes, codebooks, scales);

    int smem_bytes = STAGES * STAGE_BYTES;   // 144 KB
    cudaFuncSetAttribute(gemm_kernel, cudaFuncAttributeMaxDynamicSharedMemorySize, smem_bytes);
    gemm_kernel<<<GRID, 256, smem_bytes>>>(bias, out);
}

// round 12
// speedup vs baseline: 1.0287x; 1.0195x over previous
#include <cuda_runtime.h>
#include <cuda_fp16.h>
#include <cstdint>

// ---------------------------------------------------------------------------
// Problem constants
// ---------------------------------------------------------------------------
#define IN_F   4096
#define OUT_F  4096
#define NBLKS  128      // IN_F / 32
#define MROWS  16384    // 4 * 4096 tokens

// Scratch (allocation-free rule: __device__ globals)
__device__ float  g_Q[NBLKS * 32 * 32];             // 512 KB
__device__ __half g_W2h[(size_t)OUT_F * IN_F];      // 32 MB  rotated+dequantized W, fp16
__device__ __half g_Xh[(size_t)MROWS * IN_F];       // 128 MB x in fp16

// ---------------------------------------------------------------------------
// Helpers
// ---------------------------------------------------------------------------
__device__ __forceinline__ uint32_t smem_u32(const void* p) {
    uint32_t a;
    asm("{ .reg .u64 t; cvta.to.shared.u64 t, %1; cvt.u32.u64 %0, t; }" : "=r"(a) : "l"(p));
    return a;
}

__device__ __forceinline__ void cp16(uint32_t s, const void* g) {
    asm volatile("cp.async.cg.shared.global [%0], [%1], 16;" :: "r"(s), "l"(g));
}
#define CP_COMMIT() asm volatile("cp.async.commit_group;" ::: "memory")
#define CP_WAIT(n)  asm volatile("cp.async.wait_group %0;" :: "n"(n) : "memory")

#define LDM_X4(R, addr) \
    asm volatile("ldmatrix.sync.aligned.m8n8.x4.shared.b16 {%0,%1,%2,%3}, [%4];" \
                 : "=r"((R)[0]), "=r"((R)[1]), "=r"((R)[2]), "=r"((R)[3]) : "r"(addr))

__device__ __forceinline__ void mma_f16(float c[4], const uint32_t a[4], uint32_t b0, uint32_t b1) {
    asm volatile(
        "mma.sync.aligned.m16n8k16.row.col.f32.f16.f16.f32 "
        "{%0,%1,%2,%3}, {%4,%5,%6,%7}, {%8,%9}, {%0,%1,%2,%3};"
        : "+f"(c[0]), "+f"(c[1]), "+f"(c[2]), "+f"(c[3])
        : "r"(a[0]), "r"(a[1]), "r"(a[2]), "r"(a[3]), "r"(b0), "r"(b1));
}

// ---------------------------------------------------------------------------
// Kernel 1: Cayley  Q = (I-S)^{-1}(I+S)   (Gauss-Jordan, diag-dominant, no pivot)
// ---------------------------------------------------------------------------
__global__ void cayley_kernel(const float* __restrict__ oft_r) {
    __shared__ float A[32][33];
    __shared__ float Bm[32][33];
    int n = blockIdx.x;
    int j = threadIdx.x, i = threadIdx.y;
    const float* R = oft_r + n * 1024;
    float s  = 0.5f * (R[i * 32 + j] - R[j * 32 + i]);
    float id = (i == j) ? 1.0f : 0.0f;
    A[i][j]  = id - s;
    Bm[i][j] = id + s;
    __syncthreads();
    for (int k = 0; k < 32; k++) {
        float fac = A[i][k] / A[k][k];
        __syncthreads();
        if (i != k) {
            A[i][j]  = fmaf(-fac, A[k][j],  A[i][j]);
            Bm[i][j] = fmaf(-fac, Bm[k][j], Bm[i][j]);
        }
        __syncthreads();
    }
    g_Q[n * 1024 + i * 32 + j] = Bm[i][j] / A[i][i];
}

// ---------------------------------------------------------------------------
// Kernel 2 (fused prep): blocks [0, DBLKS) dequant + fold rotation (fp16 out)
// — launched FIRST so their gather-latency warps occupy SMs from t=0 —
// blocks [DBLKS, DBLKS+XBLKS) convert x -> fp16 (DRAM-streaming, fills in
// behind the dequant warps).
// ---------------------------------------------------------------------------
#define DBLKS 65536     // NBLKS * OUT_F/8
#define XBLKS 65536     // MROWS*IN_F / (256*4)

__global__ __launch_bounds__(256) void prep_kernel(
    const float* __restrict__ x, const int* __restrict__ codes,
    const float* __restrict__ codebooks, const float* __restrict__ scales)
{
    __shared__ float Qs[32][33];
    int blk = blockIdx.x;
    if (blk >= DBLKS) {
        size_t i = ((size_t)(blk - DBLKS) * 256 + threadIdx.x) * 4;
        float4 v = *(const float4*)(x + i);
        *(__half2*)(g_Xh + i)     = __floats2half2_rn(v.x, v.y);
        *(__half2*)(g_Xh + i + 2) = __floats2half2_rn(v.z, v.w);
        return;
    }
    int n = blk & 127;                 // 0..127
    int obase = (blk >> 7) * 8;
    int tid = threadIdx.x;
    int w = tid >> 5, lane = tid & 31;

    for (int idx = tid; idx < 1024; idx += 256)
        Qs[idx >> 5][idx & 31] = g_Q[n * 1024 + idx];
    __syncthreads();

    int o = obase + w;
    int grp = 4 * n + (lane >> 3);
    int code = codes[o * 512 + grp];
    float wv = codebooks[code * 8 + (lane & 7)];

    float acc = 0.f;
    #pragma unroll
    for (int kk = 0; kk < 32; kk++) {
        float wk = __shfl_sync(0xFFFFFFFFu, wv, kk);
        acc = fmaf(Qs[lane][kk], wk, acc);
    }
    acc *= scales[o];
    g_W2h[(size_t)o * IN_F + n * 32 + lane] = __float2half_rn(acc);
}

// ---------------------------------------------------------------------------
// Kernel 3: fp16 mma.sync GEMM   out[M,O] = x[M,K] @ W2[O,K]^T + bias (fp32 acc)
// R9 base (proven 1339us): CTA 128x256, 256 threads (8 warps 2x4), warp tile
// 64x64, KBLK=64 (4 k16 substeps/stage), register fragment double-buffering,
// 128B-row j^(row&7) swizzle. THIS ROUND: STAGES 3->4 (192KB SMEM, CP_WAIT(2),
// prefetch distance 3 k-iters) to absorb fill-latency jitter at handoffs.
// RF: ~225 regs x 256 thr = 58K < 64K (standing check).
// ---------------------------------------------------------------------------
#define STAGES 4
#define KBLK   64
#define TM     128
#define TN     256
#define KITERS (IN_F / KBLK)            // 64
#define A_BYTES (TM * KBLK * 2)         // 16 KB
#define B_BYTES (TN * KBLK * 2)         // 32 KB
#define STAGE_BYTES (A_BYTES + B_BYTES) // 48 KB

__device__ __forceinline__ uint32_t swz(int row, int j) {
    return (uint32_t)(row * 128 + ((j ^ (row & 7)) << 4));
}

__device__ __forceinline__ void stage_fill(uint32_t sb,
        const __half* gA, const __half* gB, uint32_t so0, int kb)
{
    #pragma unroll
    for (int p = 0; p < 4; p++)
        cp16(sb + so0 + p * 4096,           gA + (size_t)p * 32 * IN_F + kb);
    #pragma unroll
    for (int p = 0; p < 8; p++)
        cp16(sb + A_BYTES + so0 + p * 4096, gB + (size_t)p * 32 * IN_F + kb);
}

__device__ __forceinline__ void frag_load(uint32_t a[4][4], uint32_t b[4][4],
                                          uint32_t sb, uint32_t aoff, uint32_t boff)
{
    #pragma unroll
    for (int mi = 0; mi < 4; mi++) LDM_X4(a[mi], sb + aoff + mi * 2048);
    #pragma unroll
    for (int p = 0; p < 4; p++)    LDM_X4(b[p], sb + A_BYTES + boff + p * 2048);
}

__device__ __forceinline__ void mma_block(float acc[4][8][4],
                                          const uint32_t a[4][4], const uint32_t b[4][4])
{
    #pragma unroll
    for (int mi = 0; mi < 4; mi++)
        #pragma unroll
        for (int p = 0; p < 4; p++) {
            mma_f16(acc[mi][2 * p],     a[mi], b[p][0], b[p][2]);
            mma_f16(acc[mi][2 * p + 1], a[mi], b[p][1], b[p][3]);
        }
}

__global__ __launch_bounds__(256, 1)
void gemm_kernel(const float* __restrict__ bias, float* __restrict__ out)
{
    extern __shared__ char smem[];
    uint32_t sbase = smem_u32(smem);

    int tid  = threadIdx.x;
    int wid  = tid >> 5, lane = tid & 31;
    int g    = lane >> 2, tig = lane & 3;
    int lr   = lane & 7;                // ldmatrix row-within-matrix
    int q    = lane >> 3;               // ldmatrix matrix index 0..3
    int wm   = (wid >> 2) * 64;         // warp M offset (2 rows of warps)
    int wn   = (wid & 3) * 64;          // warp N offset (4 cols of warps)
    int nbase = blockIdx.x * TN;
    int mbase = blockIdx.y * TM;

    // ldmatrix offsets: substep s (k16) uses 16B chunks 2s, 2s+1.
    int ra = wm + lr + ((q & 1) << 3);
    int rb = wn + lr + ((q & 1) << 3);
    int ja = q >> 1;
    uint32_t aoff[4], boff[4];
    #pragma unroll
    for (int s = 0; s < 4; s++) {
        aoff[s] = swz(ra, 2 * s + ja);
        boff[s] = swz(rb, 2 * s + ja);
    }

    // Global load mapping: thread -> (row r0 = tid>>3, chunk j0 = tid&7).
    int r0 = tid >> 3, j0 = tid & 7;
    const __half* gA = g_Xh  + (size_t)(mbase + r0) * IN_F + j0 * 8;
    const __half* gB = g_W2h + (size_t)(nbase + r0) * IN_F + j0 * 8;
    uint32_t so0 = swz(r0, j0);

    float acc[4][8][4];
    #pragma unroll
    for (int mi = 0; mi < 4; mi++)
        #pragma unroll
        for (int ni = 0; ni < 8; ni++)
            #pragma unroll
            for (int p = 0; p < 4; p++) acc[mi][ni][p] = 0.f;

    // Prologue: fill stages 0,1,2
    #pragma unroll
    for (int s = 0; s < STAGES - 1; s++) {
        stage_fill(sbase + s * STAGE_BYTES, gA, gB, so0, s * KBLK);
        CP_COMMIT();
    }
    CP_WAIT(2);
    __syncthreads();

    uint32_t fa[2][4][4], fb[2][4][4];
    frag_load(fa[0], fb[0], sbase, aoff[0], boff[0]);

    for (int k = 0; k < KITERS; k++) {
        uint32_t sb_read = sbase + (k & 3) * STAGE_BYTES;

        // Fill stage k+3 into buffer (k+3)&3 == (k-1)&3 (readers done at the
        // iter k-1 barrier). One commit per k-iter, unconditionally.
        int kl = k + STAGES - 1;
        if (kl < KITERS)
            stage_fill(sbase + (kl & 3) * STAGE_BYTES, gA, gB, so0, kl * KBLK);
        CP_COMMIT();

        #pragma unroll
        for (int s = 0; s < 4; s++) {
            if (s < 3) {
                frag_load(fa[(s + 1) & 1], fb[(s + 1) & 1], sb_read, aoff[s + 1], boff[s + 1]);
            } else {
                CP_WAIT(2);                  // stage k+1 landed (>=2 groups stay in flight)
                __syncthreads();
                if (k + 1 < KITERS)
                    frag_load(fa[0], fb[0], sbase + ((k + 1) & 3) * STAGE_BYTES,
                              aoff[0], boff[0]);
            }
            mma_block(acc, fa[s & 1], fb[s & 1]);
        }
    }

    // Epilogue: direct store + bias
    #pragma unroll
    for (int mi = 0; mi < 4; mi++) {
        int r = mbase + wm + mi * 16 + g;
        #pragma unroll
        for (int ni = 0; ni < 8; ni++) {
            int col = nbase + wn + ni * 8 + tig * 2;
            float2 bv = *(const float2*)(bias + col);
            float2 v0 = make_float2(acc[mi][ni][0] + bv.x, acc[mi][ni][1] + bv.y);
            float2 v1 = make_float2(acc[mi][ni][2] + bv.x, acc[mi][ni][3] + bv.y);
            *(float2*)(out + (size_t)r * OUT_F + col)       = v0;
            *(float2*)(out + (size_t)(r + 8) * OUT_F + col) = v1;
        }
    }
}

// ---------------------------------------------------------------------------
// Launch
// ---------------------------------------------------------------------------
extern "C" void kernel_launch(void* const* d_in, const int* in_sizes, int n_in,
                              void* d_out, int out_size)
{
    const float* x         = (const float*)d_in[0];
    const float* oft_r     = (const float*)d_in[1];
    const int*   codes     = (const int*)d_in[2];
    const float* codebooks = (const float*)d_in[3];
    const float* scales    = (const float*)d_in[4];
    const float* bias      = (const float*)d_in[5];
    float*       out       = (float*)d_out;

    cayley_kernel<<<NBLKS, dim3(32, 32)>>>(oft_r);
    prep_kernel<<<DBLKS + XBLKS, 256>>>(x, codes, codebooks, scales);

    int smem_bytes = STAGES * STAGE_BYTES;   // 192 KB
    cudaFuncSetAttribute(gemm_kernel, cudaFuncAttributeMaxDynamicSharedMemorySize, smem_bytes);
    gemm_kernel<<<dim3(OUT_F / TN, MROWS / TM), 256, smem_bytes>>>(bias, out);
}